// round 7
// baseline (speedup 1.0000x reference)
#include <cuda_runtime.h>

#define SELU_SC 1.0507009873554805f
#define SELU_AL 1.6732632423543772f
#define SELU_SA (SELU_SC * SELU_AL)
#define RES_SC  0.70710678118654752440f
#define LOG2E   1.4426950408889634f
#define LN2     0.6931471805599453f
#define SC_LN2  (SELU_SC * LN2)

// standard branch-free selu (for unscaled inputs)
__device__ __forceinline__ float selu_f(float v) {
    float p = fmaxf(v, 0.0f);
    float m = fminf(v, 0.0f);
    float e = __expf(m);
    return fmaf(SELU_SA, e, fmaf(SELU_SC, p, -SELU_SA));
}

// selu on pre-scaled input s = v*log2e  (weights pre-multiplied by log2e)
__device__ __forceinline__ float selu_s(float s) {
    float p = fmaxf(s, 0.0f);
    float m = fminf(s, 0.0f);
    float e;
    asm("ex2.approx.ftz.f32 %0, %1;" : "=f"(e) : "f"(m));
    return fmaf(SELU_SA, e, fmaf(SC_LN2, p, -SELU_SA));
}

__constant__ int c_occ[21] = {65,66,67,68,69,70,71,72,73,74,75,76,77,
                              81,82,83,84,88,89,90,94};

// scratch (no cudaMalloc allowed)
__device__ float g_x[8 * 128 * 500];
__device__ float g_q[8 * 128 * 500];

// ---------------------------------------------------------------------------
// Q kernel
// ---------------------------------------------------------------------------
__global__ __launch_bounds__(128)
void q_kernel(const float* __restrict__ x, const float* __restrict__ wq,
              float* __restrict__ qout) {
    const int dg = blockIdx.x;
    const int tstart = blockIdx.y * 256;
    const int b = blockIdx.z;
    const int tid = threadIdx.x;

    __shared__ float xo[21 * 264];
    __shared__ float ws[16 * 189];

    for (int i = tid; i < 21 * 264; i += 128) {
        int o = i / 264, tt = i % 264;
        int g = tstart + tt - 4;
        xo[i] = (g >= 0 && g < 500) ? x[(b * 128 + c_occ[o]) * 500 + g] : 0.0f;
    }
    for (int i = tid; i < 16 * 189; i += 128)
        ws[i] = wq[dg * 16 * 189 + i];
    __syncthreads();

    float acc0[16], acc1[16];
#pragma unroll
    for (int i = 0; i < 16; i++) { acc0[i] = 0.0f; acc1[i] = 0.0f; }

#pragma unroll 1
    for (int o = 0; o < 21; o++) {
        float xa[9], xb[9];
#pragma unroll
        for (int k = 0; k < 9; k++) {
            xa[k] = xo[o * 264 + tid + k];
            xb[k] = xo[o * 264 + tid + 128 + k];
        }
#pragma unroll
        for (int dc = 0; dc < 16; dc++) {
#pragma unroll
            for (int k = 0; k < 9; k++) {
                float w = ws[dc * 189 + o * 9 + k];
                acc0[dc] = fmaf(xa[k], w, acc0[dc]);
                acc1[dc] = fmaf(xb[k], w, acc1[dc]);
            }
        }
    }

    const int t1 = tstart + tid;
    const int t2 = t1 + 128;
#pragma unroll
    for (int dc = 0; dc < 16; dc++) {
        int dch = dg * 16 + dc;
        if (t1 < 500) qout[(b * 128 + dch) * 500 + t1] = selu_f(acc0[dc]);
        if (t2 < 500) qout[(b * 128 + dch) * 500 + t2] = selu_f(acc1[dc]);
    }
}

// ---------------------------------------------------------------------------
// Fused layer kernel. grid (C=128, B=8), 256 threads, launch_bounds(256,5).
//   tt = tid & 127 : t-chunk (4 consecutive t, 125 active)
//   hh = tid >> 7  : head half (heads hh*4 .. hh*4+3)
// Per j: qv prefetch, K-phase (conv+selu+gate acc), V-phase (conv+selu+proj acc).
// Pointer-walked weight/q addresses.
// ---------------------------------------------------------------------------
__global__ __launch_bounds__(256, 5)
void layer_kernel(const float* __restrict__ xin,
                  const float* __restrict__ q,
                  const float* __restrict__ wk,
                  const float* __restrict__ wv,
                  const float* __restrict__ wproj,
                  float* __restrict__ xout) {
    const int c = blockIdx.x, b = blockIdx.y, tid = threadIdx.x;
    const int tt = tid & 127;
    const int hh = tid >> 7;

    __shared__ __align__(16) float xs[508];       // x row padded by 4 each side
    __shared__ __align__(16) float wks[128 * 12]; // K weights ×log2e + wproj
    __shared__ __align__(16) float wvs[128 * 12]; // V weights ×log2e
    __shared__ __align__(16) float pacc[125 * 4]; // partial acc from half 1

    const float* xrow = xin + (b * 128 + c) * 500;
    for (int i = tid; i < 508; i += 256) {
        int g = i - 4;
        xs[i] = (g >= 0 && g < 500) ? xrow[g] : 0.0f;
    }
    const float* wkr = wk + c * 1152;
    const float* wvr = wv + c * 1152;
    for (int i = tid; i < 1152; i += 256) {
        int row = i / 9, kk = i - row * 9;
        wks[row * 12 + kk] = wkr[i] * LOG2E;
        wvs[row * 12 + kk] = wvr[i] * LOG2E;
    }
    if (tid < 128) wks[tid * 12 + 9] = wproj[c * 128 + tid];
    __syncthreads();

    const bool active = (tt < 125);
    const int t0 = tt * 4;
    float acc[4] = {0.f, 0.f, 0.f, 0.f};
    float xw[12];

    if (active) {
#pragma unroll
        for (int i = 0; i < 12; i++) xw[i] = xs[t0 + i];

        const float* qp   = q + (size_t)(b * 128 + hh * 64) * 500 + t0;
        const float* krow = &wks[(hh * 64) * 12];
        const float* vrow = &wvs[(hh * 64) * 12];

#pragma unroll 1
        for (int h = 0; h < 4; h++) {
            float qk[4] = {0.f, 0.f, 0.f, 0.f};
            float pv[4] = {0.f, 0.f, 0.f, 0.f};
#pragma unroll 2
            for (int j = 0; j < 16; j++) {
                float4 qv = *reinterpret_cast<const float4*>(qp);  // prefetch

                // ---- K phase ----
                {
                    float4 ka = *reinterpret_cast<const float4*>(krow);
                    float4 kb = *reinterpret_cast<const float4*>(krow + 4);
                    float2 kc = *reinterpret_cast<const float2*>(krow + 8); // {w8, wp}
#pragma unroll
                    for (int u = 0; u < 4; u++) {
                        float k0 = ka.x * xw[u];
                        k0 = fmaf(ka.y, xw[u + 1], k0);
                        k0 = fmaf(ka.z, xw[u + 2], k0);
                        k0 = fmaf(ka.w, xw[u + 3], k0);
                        k0 = fmaf(kb.x, xw[u + 4], k0);
                        k0 = fmaf(kb.y, xw[u + 5], k0);
                        k0 = fmaf(kb.z, xw[u + 6], k0);
                        k0 = fmaf(kb.w, xw[u + 7], k0);
                        k0 = fmaf(kc.x, xw[u + 8], k0);
                        float qc = (u == 0) ? qv.x : (u == 1) ? qv.y
                                  : (u == 2) ? qv.z : qv.w;
                        qk[u] = fmaf(qc, selu_s(k0), qk[u]);
                    }
                    // ---- V phase (wp = kc.y still live) ----
                    float4 va = *reinterpret_cast<const float4*>(vrow);
                    float4 vb = *reinterpret_cast<const float4*>(vrow + 4);
                    float v8 = vrow[8];
#pragma unroll
                    for (int u = 0; u < 4; u++) {
                        float v0 = va.x * xw[u];
                        v0 = fmaf(va.y, xw[u + 1], v0);
                        v0 = fmaf(va.z, xw[u + 2], v0);
                        v0 = fmaf(va.w, xw[u + 3], v0);
                        v0 = fmaf(vb.x, xw[u + 4], v0);
                        v0 = fmaf(vb.y, xw[u + 5], v0);
                        v0 = fmaf(vb.z, xw[u + 6], v0);
                        v0 = fmaf(vb.w, xw[u + 7], v0);
                        v0 = fmaf(v8,   xw[u + 8], v0);
                        pv[u] = fmaf(kc.y, selu_s(v0), pv[u]);
                    }
                }
                krow += 12; vrow += 12; qp += 500;
            }
#pragma unroll
            for (int u = 0; u < 4; u++) {
                float gate = selu_f(0.25f * qk[u]);   // scale = d^-0.5
                acc[u] = fmaf(gate, pv[u], acc[u]);
            }
        }

        if (hh == 1) {
            float4 pa = make_float4(acc[0], acc[1], acc[2], acc[3]);
            *reinterpret_cast<float4*>(&pacc[tt * 4]) = pa;
        }
    }
    __syncthreads();

    if (active && hh == 0) {
        float4 pa = *reinterpret_cast<const float4*>(&pacc[tt * 4]);
        acc[0] += pa.x; acc[1] += pa.y; acc[2] += pa.z; acc[3] += pa.w;
        float4 res;
        res.x = (xw[4] + selu_f(acc[0])) * RES_SC;
        res.y = (xw[5] + selu_f(acc[1])) * RES_SC;
        res.z = (xw[6] + selu_f(acc[2])) * RES_SC;
        res.w = (xw[7] + selu_f(acc[3])) * RES_SC;
        *reinterpret_cast<float4*>(xout + (size_t)(b * 128 + c) * 500 + t0) = res;
    }
}

// ---------------------------------------------------------------------------
// Head
// ---------------------------------------------------------------------------
__global__ __launch_bounds__(256)
void head_kernel(const float* __restrict__ x, const float* __restrict__ wh,
                 const float* __restrict__ bh, float* __restrict__ out) {
    const int n = blockIdx.x, b = blockIdx.y, tid = threadIdx.x;
    const float4* xr = reinterpret_cast<const float4*>(x + (size_t)b * 64000);
    const float4* wr = reinterpret_cast<const float4*>(wh + (size_t)n * 64000);
    float sum = 0.0f;
    for (int i = tid; i < 16000; i += 256) {
        float4 a = xr[i], w = wr[i];
        sum += a.x * w.x + a.y * w.y + a.z * w.z + a.w * w.w;
    }
#pragma unroll
    for (int off = 16; off; off >>= 1)
        sum += __shfl_down_sync(0xffffffffu, sum, off);
    __shared__ float ps[8];
    if ((tid & 31) == 0) ps[tid >> 5] = sum;
    __syncthreads();
    if (tid < 8) {
        sum = ps[tid];
#pragma unroll
        for (int off = 4; off; off >>= 1)
            sum += __shfl_down_sync(0xffu, sum, off);
        if (tid == 0) out[b * 40 + n] = sum + bh[n];
    }
}

// ---------------------------------------------------------------------------
extern "C" void kernel_launch(void* const* d_in, const int* in_sizes, int n_in,
                              void* d_out, int out_size) {
    const float* x     = (const float*)d_in[0];
    const float* wq    = (const float*)d_in[2];  // (2,128,21,9)
    const float* wk    = (const float*)d_in[3];  // (2,16384,1,9)
    const float* wv    = (const float*)d_in[4];  // (2,16384,1,9)
    const float* wproj = (const float*)d_in[5];  // (2,128,128)
    const float* whead = (const float*)d_in[6];  // (40,64000)
    const float* bhead = (const float*)d_in[7];  // (40,)
    float* out = (float*)d_out;

    float *gx = nullptr, *gq = nullptr;
    cudaGetSymbolAddress((void**)&gx, g_x);
    cudaGetSymbolAddress((void**)&gq, g_q);

    dim3 qg(8, 2, 8);
    dim3 lg(128, 8);
    dim3 hg(40, 8);

    q_kernel<<<qg, 128>>>(x, wq, gq);
    layer_kernel<<<lg, 256>>>(x, gq, wk, wv, wproj, gx);
    q_kernel<<<qg, 128>>>(gx, wq + 24192, gq);
    layer_kernel<<<lg, 256>>>(gx, gq, wk + 147456, wv + 147456,
                              wproj + 16384, gx);
    head_kernel<<<hg, 256>>>(gx, whead, bhead, out);
}

// round 8
// speedup vs baseline: 1.0192x; 1.0192x over previous
#include <cuda_runtime.h>

#define SELU_SC 1.0507009873554805f
#define SELU_AL 1.6732632423543772f
#define SELU_SA (SELU_SC * SELU_AL)
#define RES_SC  0.70710678118654752440f
#define LOG2E   1.4426950408889634f
#define LN2     0.6931471805599453f
#define SC_LN2  (SELU_SC * LN2)

// standard branch-free selu (for unscaled inputs)
__device__ __forceinline__ float selu_f(float v) {
    float p = fmaxf(v, 0.0f);
    float m = fminf(v, 0.0f);
    float e = __expf(m);
    return fmaf(SELU_SA, e, fmaf(SELU_SC, p, -SELU_SA));
}

// selu on pre-scaled input s = v*log2e  (weights pre-multiplied by log2e)
__device__ __forceinline__ float selu_s(float s) {
    float p = fmaxf(s, 0.0f);
    float m = fminf(s, 0.0f);
    float e;
    asm("ex2.approx.ftz.f32 %0, %1;" : "=f"(e) : "f"(m));
    return fmaf(SELU_SA, e, fmaf(SC_LN2, p, -SELU_SA));
}

__constant__ int c_occ[21] = {65,66,67,68,69,70,71,72,73,74,75,76,77,
                              81,82,83,84,88,89,90,94};

// scratch (no cudaMalloc allowed)
__device__ float g_x[8 * 128 * 500];
__device__ float g_q[8 * 128 * 500];

// ---------------------------------------------------------------------------
// Q kernel
// ---------------------------------------------------------------------------
__global__ __launch_bounds__(128)
void q_kernel(const float* __restrict__ x, const float* __restrict__ wq,
              float* __restrict__ qout) {
    const int dg = blockIdx.x;
    const int tstart = blockIdx.y * 256;
    const int b = blockIdx.z;
    const int tid = threadIdx.x;

    __shared__ float xo[21 * 264];
    __shared__ float ws[16 * 189];

    for (int i = tid; i < 21 * 264; i += 128) {
        int o = i / 264, tt = i % 264;
        int g = tstart + tt - 4;
        xo[i] = (g >= 0 && g < 500) ? x[(b * 128 + c_occ[o]) * 500 + g] : 0.0f;
    }
    for (int i = tid; i < 16 * 189; i += 128)
        ws[i] = wq[dg * 16 * 189 + i];
    __syncthreads();

    float acc0[16], acc1[16];
#pragma unroll
    for (int i = 0; i < 16; i++) { acc0[i] = 0.0f; acc1[i] = 0.0f; }

#pragma unroll 1
    for (int o = 0; o < 21; o++) {
        float xa[9], xb[9];
#pragma unroll
        for (int k = 0; k < 9; k++) {
            xa[k] = xo[o * 264 + tid + k];
            xb[k] = xo[o * 264 + tid + 128 + k];
        }
#pragma unroll
        for (int dc = 0; dc < 16; dc++) {
#pragma unroll
            for (int k = 0; k < 9; k++) {
                float w = ws[dc * 189 + o * 9 + k];
                acc0[dc] = fmaf(xa[k], w, acc0[dc]);
                acc1[dc] = fmaf(xb[k], w, acc1[dc]);
            }
        }
    }

    const int t1 = tstart + tid;
    const int t2 = t1 + 128;
#pragma unroll
    for (int dc = 0; dc < 16; dc++) {
        int dch = dg * 16 + dc;
        if (t1 < 500) qout[(b * 128 + dch) * 500 + t1] = selu_f(acc0[dc]);
        if (t2 < 500) qout[(b * 128 + dch) * 500 + t2] = selu_f(acc1[dc]);
    }
}

// ---------------------------------------------------------------------------
// Fused layer kernel. grid (C=128, B=8), 256 threads.
//   tt = tid & 127 : t-chunk (4 consecutive t, 125 active)
//   hh = tid >> 7  : head half (heads hh*4 .. hh*4+3)
// R6 interleaved body (8 independent FMA chains per j) with immediate selu
// application (no kk/vv staging arrays) to cut live registers.
// ---------------------------------------------------------------------------
__global__ __launch_bounds__(256, 5)
void layer_kernel(const float* __restrict__ xin,
                  const float* __restrict__ q,
                  const float* __restrict__ wk,
                  const float* __restrict__ wv,
                  const float* __restrict__ wproj,
                  float* __restrict__ xout) {
    const int c = blockIdx.x, b = blockIdx.y, tid = threadIdx.x;
    const int tt = tid & 127;
    const int hh = tid >> 7;

    __shared__ __align__(16) float xs[508];       // x row padded by 4 each side
    __shared__ __align__(16) float wks[128 * 12]; // K weights ×log2e + wproj
    __shared__ __align__(16) float wvs[128 * 12]; // V weights ×log2e
    __shared__ __align__(16) float pacc[125 * 4]; // partial acc from half 1

    const float* xrow = xin + (b * 128 + c) * 500;
    for (int i = tid; i < 508; i += 256) {
        int g = i - 4;
        xs[i] = (g >= 0 && g < 500) ? xrow[g] : 0.0f;
    }
    const float* wkr = wk + c * 1152;
    const float* wvr = wv + c * 1152;
    for (int i = tid; i < 1152; i += 256) {
        int row = i / 9, kk = i - row * 9;
        wks[row * 12 + kk] = wkr[i] * LOG2E;
        wvs[row * 12 + kk] = wvr[i] * LOG2E;
    }
    if (tid < 128) wks[tid * 12 + 9] = wproj[c * 128 + tid];
    __syncthreads();

    const bool active = (tt < 125);
    const int t0 = tt * 4;
    float acc[4] = {0.f, 0.f, 0.f, 0.f};
    float xw[12];

    if (active) {
#pragma unroll
        for (int i = 0; i < 12; i++) xw[i] = xs[t0 + i];

        const float* qbase = q + (size_t)(b * 128 + hh * 64) * 500 + t0;
        const int d0 = hh * 64;

#pragma unroll 1
        for (int h = 0; h < 4; h++) {
            float qk[4] = {0.f, 0.f, 0.f, 0.f};
            float pv[4] = {0.f, 0.f, 0.f, 0.f};
#pragma unroll 4
            for (int j = 0; j < 16; j++) {
                const int dd = d0 + h * 16 + j;
                const float* krow = &wks[dd * 12];
                const float* vrow = &wvs[dd * 12];

                float4 qv = *reinterpret_cast<const float4*>(qbase + (h * 16 + j) * 500);
                const float* qvf = reinterpret_cast<const float*>(&qv);

                float4 ka = *reinterpret_cast<const float4*>(krow);
                float4 kb = *reinterpret_cast<const float4*>(krow + 4);
                float2 kc = *reinterpret_cast<const float2*>(krow + 8); // {w8, wp}
                float4 va = *reinterpret_cast<const float4*>(vrow);
                float4 vb = *reinterpret_cast<const float4*>(vrow + 4);
                float v8 = vrow[8];

#pragma unroll
                for (int u = 0; u < 4; u++) {
                    float k0 = ka.x * xw[u];
                    float v0 = va.x * xw[u];
                    k0 = fmaf(ka.y, xw[u + 1], k0);  v0 = fmaf(va.y, xw[u + 1], v0);
                    k0 = fmaf(ka.z, xw[u + 2], k0);  v0 = fmaf(va.z, xw[u + 2], v0);
                    k0 = fmaf(ka.w, xw[u + 3], k0);  v0 = fmaf(va.w, xw[u + 3], v0);
                    k0 = fmaf(kb.x, xw[u + 4], k0);  v0 = fmaf(vb.x, xw[u + 4], v0);
                    k0 = fmaf(kb.y, xw[u + 5], k0);  v0 = fmaf(vb.y, xw[u + 5], v0);
                    k0 = fmaf(kb.z, xw[u + 6], k0);  v0 = fmaf(vb.z, xw[u + 6], v0);
                    k0 = fmaf(kb.w, xw[u + 7], k0);  v0 = fmaf(vb.w, xw[u + 7], v0);
                    k0 = fmaf(kc.x, xw[u + 8], k0);  v0 = fmaf(v8,   xw[u + 8], v0);
                    qk[u] = fmaf(qvf[u], selu_s(k0), qk[u]);
                    pv[u] = fmaf(kc.y,   selu_s(v0), pv[u]);
                }
            }
#pragma unroll
            for (int u = 0; u < 4; u++) {
                float gate = selu_f(0.25f * qk[u]);   // scale = d^-0.5
                acc[u] = fmaf(gate, pv[u], acc[u]);
            }
        }

        if (hh == 1) {
            float4 pa = make_float4(acc[0], acc[1], acc[2], acc[3]);
            *reinterpret_cast<float4*>(&pacc[tt * 4]) = pa;
        }
    }
    __syncthreads();

    if (active && hh == 0) {
        float4 pa = *reinterpret_cast<const float4*>(&pacc[tt * 4]);
        acc[0] += pa.x; acc[1] += pa.y; acc[2] += pa.z; acc[3] += pa.w;
        float4 res;
        res.x = (xw[4] + selu_f(acc[0])) * RES_SC;
        res.y = (xw[5] + selu_f(acc[1])) * RES_SC;
        res.z = (xw[6] + selu_f(acc[2])) * RES_SC;
        res.w = (xw[7] + selu_f(acc[3])) * RES_SC;
        *reinterpret_cast<float4*>(xout + (size_t)(b * 128 + c) * 500 + t0) = res;
    }
}

// ---------------------------------------------------------------------------
// Head
// ---------------------------------------------------------------------------
__global__ __launch_bounds__(256)
void head_kernel(const float* __restrict__ x, const float* __restrict__ wh,
                 const float* __restrict__ bh, float* __restrict__ out) {
    const int n = blockIdx.x, b = blockIdx.y, tid = threadIdx.x;
    const float4* xr = reinterpret_cast<const float4*>(x + (size_t)b * 64000);
    const float4* wr = reinterpret_cast<const float4*>(wh + (size_t)n * 64000);
    float sum = 0.0f;
    for (int i = tid; i < 16000; i += 256) {
        float4 a = xr[i], w = wr[i];
        sum += a.x * w.x + a.y * w.y + a.z * w.z + a.w * w.w;
    }
#pragma unroll
    for (int off = 16; off; off >>= 1)
        sum += __shfl_down_sync(0xffffffffu, sum, off);
    __shared__ float ps[8];
    if ((tid & 31) == 0) ps[tid >> 5] = sum;
    __syncthreads();
    if (tid < 8) {
        sum = ps[tid];
#pragma unroll
        for (int off = 4; off; off >>= 1)
            sum += __shfl_down_sync(0xffu, sum, off);
        if (tid == 0) out[b * 40 + n] = sum + bh[n];
    }
}

// ---------------------------------------------------------------------------
extern "C" void kernel_launch(void* const* d_in, const int* in_sizes, int n_in,
                              void* d_out, int out_size) {
    const float* x     = (const float*)d_in[0];
    const float* wq    = (const float*)d_in[2];  // (2,128,21,9)
    const float* wk    = (const float*)d_in[3];  // (2,16384,1,9)
    const float* wv    = (const float*)d_in[4];  // (2,16384,1,9)
    const float* wproj = (const float*)d_in[5];  // (2,128,128)
    const float* whead = (const float*)d_in[6];  // (40,64000)
    const float* bhead = (const float*)d_in[7];  // (40,)
    float* out = (float*)d_out;

    float *gx = nullptr, *gq = nullptr;
    cudaGetSymbolAddress((void**)&gx, g_x);
    cudaGetSymbolAddress((void**)&gq, g_q);

    dim3 qg(8, 2, 8);
    dim3 lg(128, 8);
    dim3 hg(40, 8);

    q_kernel<<<qg, 128>>>(x, wq, gq);
    layer_kernel<<<lg, 256>>>(x, gq, wk, wv, wproj, gx);
    q_kernel<<<qg, 128>>>(gx, wq + 24192, gq);
    layer_kernel<<<lg, 256>>>(gx, gq, wk + 147456, wv + 147456,
                              wproj + 16384, gx);
    head_kernel<<<hg, 256>>>(gx, whead, bhead, out);
}

// round 9
// speedup vs baseline: 1.1100x; 1.0891x over previous
#include <cuda_runtime.h>

#define SELU_SC 1.0507009873554805f
#define SELU_AL 1.6732632423543772f
#define SELU_SA (SELU_SC * SELU_AL)
#define RES_SC  0.70710678118654752440f
#define LOG2E   1.4426950408889634f
#define LN2     0.6931471805599453f
#define SC_LN2  (SELU_SC * LN2)
#define Q_SC    (0.25f * LOG2E)

// standard branch-free selu (for unscaled inputs)
__device__ __forceinline__ float selu_f(float v) {
    float p = fmaxf(v, 0.0f);
    float m = fminf(v, 0.0f);
    float e = __expf(m);
    return fmaf(SELU_SA, e, fmaf(SELU_SC, p, -SELU_SA));
}

// selu on pre-scaled input s = v*log2e  (weights pre-multiplied by log2e)
__device__ __forceinline__ float selu_s(float s) {
    float p = fmaxf(s, 0.0f);
    float m = fminf(s, 0.0f);
    float e;
    asm("ex2.approx.ftz.f32 %0, %1;" : "=f"(e) : "f"(m));
    return fmaf(SELU_SA, e, fmaf(SC_LN2, p, -SELU_SA));
}

__constant__ int c_occ[21] = {65,66,67,68,69,70,71,72,73,74,75,76,77,
                              81,82,83,84,88,89,90,94};

// scratch (no cudaMalloc allowed)
__device__ float g_x[8 * 128 * 500];
__device__ float g_q[8 * 128 * 500];

// ---------------------------------------------------------------------------
// Q kernel
// ---------------------------------------------------------------------------
__global__ __launch_bounds__(128)
void q_kernel(const float* __restrict__ x, const float* __restrict__ wq,
              float* __restrict__ qout) {
    const int dg = blockIdx.x;
    const int tstart = blockIdx.y * 256;
    const int b = blockIdx.z;
    const int tid = threadIdx.x;

    __shared__ float xo[21 * 264];
    __shared__ float ws[16 * 189];

    for (int i = tid; i < 21 * 264; i += 128) {
        int o = i / 264, tt = i % 264;
        int g = tstart + tt - 4;
        xo[i] = (g >= 0 && g < 500) ? x[(b * 128 + c_occ[o]) * 500 + g] : 0.0f;
    }
    for (int i = tid; i < 16 * 189; i += 128)
        ws[i] = wq[dg * 16 * 189 + i];
    __syncthreads();

    float acc0[16], acc1[16];
#pragma unroll
    for (int i = 0; i < 16; i++) { acc0[i] = 0.0f; acc1[i] = 0.0f; }

#pragma unroll 1
    for (int o = 0; o < 21; o++) {
        float xa[9], xb[9];
#pragma unroll
        for (int k = 0; k < 9; k++) {
            xa[k] = xo[o * 264 + tid + k];
            xb[k] = xo[o * 264 + tid + 128 + k];
        }
#pragma unroll
        for (int dc = 0; dc < 16; dc++) {
#pragma unroll
            for (int k = 0; k < 9; k++) {
                float w = ws[dc * 189 + o * 9 + k];
                acc0[dc] = fmaf(xa[k], w, acc0[dc]);
                acc1[dc] = fmaf(xb[k], w, acc1[dc]);
            }
        }
    }

    const int t1 = tstart + tid;
    const int t2 = t1 + 128;
#pragma unroll
    for (int dc = 0; dc < 16; dc++) {
        int dch = dg * 16 + dc;
        if (t1 < 500) qout[(b * 128 + dch) * 500 + t1] = selu_f(acc0[dc]);
        if (t2 < 500) qout[(b * 128 + dch) * 500 + t2] = selu_f(acc1[dc]);
    }
}

// ---------------------------------------------------------------------------
// Fused layer kernel (R6 structure). grid (C=128, B=8), 256 threads.
//   tt = tid & 127 : t-chunk (4 consecutive t, 125 active)
//   hh = tid >> 7  : head half (heads hh*4 .. hh*4+3)
// wks row (12 floats): [k0..k7][k8, wp, v8, pad]  -> kc4 = LDS.128
// wvs row (12 floats): [v0..v7][unused...]
// Per j: 3 LDS.128 (K side) + 2 LDS.128 (V side) + LDG.128 (q) = 5 LDS.
// ---------------------------------------------------------------------------
__global__ __launch_bounds__(256)
void layer_kernel(const float* __restrict__ xin,
                  const float* __restrict__ q,
                  const float* __restrict__ wk,
                  const float* __restrict__ wv,
                  const float* __restrict__ wproj,
                  float* __restrict__ xout) {
    const int c = blockIdx.x, b = blockIdx.y, tid = threadIdx.x;
    const int tt = tid & 127;
    const int hh = tid >> 7;

    __shared__ __align__(16) float xs[508];       // x row padded by 4 each side
    __shared__ __align__(16) float wks[128 * 12]; // K w ×log2e + {k8,wp,v8}
    __shared__ __align__(16) float wvs[128 * 12]; // V w ×log2e (first 8)
    __shared__ __align__(16) float pacc[125 * 4]; // partial acc from half 1

    const float* xrow = xin + (b * 128 + c) * 500;
    for (int i = tid; i < 508; i += 256) {
        int g = i - 4;
        xs[i] = (g >= 0 && g < 500) ? xrow[g] : 0.0f;
    }
    const float* wkr = wk + c * 1152;
    const float* wvr = wv + c * 1152;
    for (int i = tid; i < 1152; i += 256) {
        int row = i / 9, kk = i - row * 9;
        wks[row * 12 + kk] = wkr[i] * LOG2E;
        float wvv = wvr[i] * LOG2E;
        if (kk < 8) wvs[row * 12 + kk] = wvv;
        else        wks[row * 12 + 10] = wvv;     // v8 slot
    }
    if (tid < 128) wks[tid * 12 + 9] = wproj[c * 128 + tid];
    __syncthreads();

    const bool active = (tt < 125);
    const int t0 = tt * 4;
    float acc[4] = {0.f, 0.f, 0.f, 0.f};
    float xw[12];

    if (active) {
#pragma unroll
        for (int i = 0; i < 12; i++) xw[i] = xs[t0 + i];

        const float* qbase = q + (size_t)(b * 128 + hh * 64) * 500 + t0;
        const int d0 = hh * 64;

#pragma unroll 1
        for (int h = 0; h < 4; h++) {
            float qk[4] = {0.f, 0.f, 0.f, 0.f};
            float pv[4] = {0.f, 0.f, 0.f, 0.f};
#pragma unroll 4
            for (int j = 0; j < 16; j++) {
                const int dd = d0 + h * 16 + j;
                const float* krow = &wks[dd * 12];
                const float* vrow = &wvs[dd * 12];

                float4 ka  = *reinterpret_cast<const float4*>(krow);
                float4 kb  = *reinterpret_cast<const float4*>(krow + 4);
                float4 kc4 = *reinterpret_cast<const float4*>(krow + 8); // {k8,wp,v8,-}
                float4 va  = *reinterpret_cast<const float4*>(vrow);
                float4 vb  = *reinterpret_cast<const float4*>(vrow + 4);

                float kk[4], vv[4];
#pragma unroll
                for (int u = 0; u < 4; u++) {
                    float k0 = ka.x * xw[u];
                    float v0 = va.x * xw[u];
                    k0 = fmaf(ka.y, xw[u + 1], k0);  v0 = fmaf(va.y, xw[u + 1], v0);
                    k0 = fmaf(ka.z, xw[u + 2], k0);  v0 = fmaf(va.z, xw[u + 2], v0);
                    k0 = fmaf(ka.w, xw[u + 3], k0);  v0 = fmaf(va.w, xw[u + 3], v0);
                    k0 = fmaf(kb.x, xw[u + 4], k0);  v0 = fmaf(vb.x, xw[u + 4], v0);
                    k0 = fmaf(kb.y, xw[u + 5], k0);  v0 = fmaf(vb.y, xw[u + 5], v0);
                    k0 = fmaf(kb.z, xw[u + 6], k0);  v0 = fmaf(vb.z, xw[u + 6], v0);
                    k0 = fmaf(kb.w, xw[u + 7], k0);  v0 = fmaf(vb.w, xw[u + 7], v0);
                    k0 = fmaf(kc4.x, xw[u + 8], k0); v0 = fmaf(kc4.z, xw[u + 8], v0);
                    kk[u] = k0; vv[u] = v0;
                }

                float4 qv = *reinterpret_cast<const float4*>(qbase + (h * 16 + j) * 500);
                qk[0] = fmaf(qv.x, selu_s(kk[0]), qk[0]);
                qk[1] = fmaf(qv.y, selu_s(kk[1]), qk[1]);
                qk[2] = fmaf(qv.z, selu_s(kk[2]), qk[2]);
                qk[3] = fmaf(qv.w, selu_s(kk[3]), qk[3]);

                float wp = kc4.y;
#pragma unroll
                for (int u = 0; u < 4; u++)
                    pv[u] = fmaf(wp, selu_s(vv[u]), pv[u]);
            }
#pragma unroll
            for (int u = 0; u < 4; u++) {
                float gate = selu_s(Q_SC * qk[u]);   // selu(0.25*qk)
                acc[u] = fmaf(gate, pv[u], acc[u]);
            }
        }

        if (hh == 1) {
            float4 pa = make_float4(acc[0], acc[1], acc[2], acc[3]);
            *reinterpret_cast<float4*>(&pacc[tt * 4]) = pa;
        }
    }
    __syncthreads();

    if (active && hh == 0) {
        float4 pa = *reinterpret_cast<const float4*>(&pacc[tt * 4]);
        acc[0] += pa.x; acc[1] += pa.y; acc[2] += pa.z; acc[3] += pa.w;
        float4 res;
        res.x = (xw[4] + selu_f(acc[0])) * RES_SC;
        res.y = (xw[5] + selu_f(acc[1])) * RES_SC;
        res.z = (xw[6] + selu_f(acc[2])) * RES_SC;
        res.w = (xw[7] + selu_f(acc[3])) * RES_SC;
        *reinterpret_cast<float4*>(xout + (size_t)(b * 128 + c) * 500 + t0) = res;
    }
}

// ---------------------------------------------------------------------------
// Head
// ---------------------------------------------------------------------------
__global__ __launch_bounds__(256)
void head_kernel(const float* __restrict__ x, const float* __restrict__ wh,
                 const float* __restrict__ bh, float* __restrict__ out) {
    const int n = blockIdx.x, b = blockIdx.y, tid = threadIdx.x;
    const float4* xr = reinterpret_cast<const float4*>(x + (size_t)b * 64000);
    const float4* wr = reinterpret_cast<const float4*>(wh + (size_t)n * 64000);
    float sum = 0.0f;
    for (int i = tid; i < 16000; i += 256) {
        float4 a = xr[i], w = wr[i];
        sum += a.x * w.x + a.y * w.y + a.z * w.z + a.w * w.w;
    }
#pragma unroll
    for (int off = 16; off; off >>= 1)
        sum += __shfl_down_sync(0xffffffffu, sum, off);
    __shared__ float ps[8];
    if ((tid & 31) == 0) ps[tid >> 5] = sum;
    __syncthreads();
    if (tid < 8) {
        sum = ps[tid];
#pragma unroll
        for (int off = 4; off; off >>= 1)
            sum += __shfl_down_sync(0xffu, sum, off);
        if (tid == 0) out[b * 40 + n] = sum + bh[n];
    }
}

// ---------------------------------------------------------------------------
extern "C" void kernel_launch(void* const* d_in, const int* in_sizes, int n_in,
                              void* d_out, int out_size) {
    const float* x     = (const float*)d_in[0];
    const float* wq    = (const float*)d_in[2];  // (2,128,21,9)
    const float* wk    = (const float*)d_in[3];  // (2,16384,1,9)
    const float* wv    = (const float*)d_in[4];  // (2,16384,1,9)
    const float* wproj = (const float*)d_in[5];  // (2,128,128)
    const float* whead = (const float*)d_in[6];  // (40,64000)
    const float* bhead = (const float*)d_in[7];  // (40,)
    float* out = (float*)d_out;

    float *gx = nullptr, *gq = nullptr;
    cudaGetSymbolAddress((void**)&gx, g_x);
    cudaGetSymbolAddress((void**)&gq, g_q);

    dim3 qg(8, 2, 8);
    dim3 lg(128, 8);
    dim3 hg(40, 8);

    q_kernel<<<qg, 128>>>(x, wq, gq);
    layer_kernel<<<lg, 256>>>(x, gq, wk, wv, wproj, gx);
    q_kernel<<<qg, 128>>>(gx, wq + 24192, gq);
    layer_kernel<<<lg, 256>>>(gx, gq, wk + 147456, wv + 147456,
                              wproj + 16384, gx);
    head_kernel<<<hg, 256>>>(gx, whead, bhead, out);
}